// round 15
// baseline (speedup 1.0000x reference)
#include <cuda_runtime.h>
#include <cuda_bf16.h>
#include <cstdint>

// Problem constants
#define BATCH 128
#define NSEQ  384
#define MSEQ  384
#define DDIM  128
#define INF_V 1000000.0f

// g_D TRANSPOSED: g_D[b][j][i] = ||a_i - b_j||^2, contiguous in i.
__device__ float g_D[(size_t)BATCH * MSEQ * NSEQ];

// ---------------------------------------------------------------------------
// PTX helpers — generic compute_80+ PTX only (compute_103 generic stage;
// tcgen05 / arch-specific ops are NOT available in this devloop).
// ---------------------------------------------------------------------------
__device__ __forceinline__ uint32_t smem_u32(const void* p) {
    uint32_t a;
    asm("{ .reg .u64 t; cvta.to.shared.u64 t, %1; cvt.u32.u64 %0, t; }" : "=r"(a) : "l"(p));
    return a;
}
__device__ __forceinline__ uint32_t f2bf2(float lo, float hi) {   // pack bf16x2 {hi,lo}
    uint32_t r;
    asm("cvt.rn.bf16x2.f32 %0, %1, %2;" : "=r"(r) : "f"(hi), "f"(lo));
    return r;
}
__device__ __forceinline__ void ldsm4(uint32_t& r0, uint32_t& r1, uint32_t& r2,
                                      uint32_t& r3, uint32_t addr) {
    asm volatile("ldmatrix.sync.aligned.m8n8.x4.shared.b16 {%0,%1,%2,%3}, [%4];"
                 : "=r"(r0), "=r"(r1), "=r"(r2), "=r"(r3) : "r"(addr));
}
__device__ __forceinline__ void mma16816(float* c, const uint32_t* a, const uint32_t* b) {
    asm volatile("mma.sync.aligned.m16n8k16.row.col.f32.bf16.bf16.f32 "
                 "{%0,%1,%2,%3}, {%4,%5,%6,%7}, {%8,%9}, {%0,%1,%2,%3};"
                 : "+f"(c[0]), "+f"(c[1]), "+f"(c[2]), "+f"(c[3])
                 : "r"(a[0]), "r"(a[1]), "r"(a[2]), "r"(a[3]), "r"(b[0]), "r"(b[1]));
}
__device__ __forceinline__ void cp_async4(uint32_t dst, const void* src, uint32_t srcsz) {
    asm volatile("cp.async.ca.shared.global [%0], [%1], 4, %2;"
                 :: "r"(dst), "l"(src), "r"(srcsz) : "memory");
}
#define CP_COMMIT() asm volatile("cp.async.commit_group;" ::: "memory")
#define CP_WAIT1()  asm volatile("cp.async.wait_group 1;" ::: "memory")

// ---------------------------------------------------------------------------
// Kernel 1: fused norms + pairwise distances via bf16 HMMA (unchanged R11).
// ---------------------------------------------------------------------------
#define TILE 128
#define KH   64
#define SMSTR 72

struct __align__(16) DistSmem {
    __nv_bfloat16 bmat[TILE * SMSTR];
    __nv_bfloat16 amat[TILE * SMSTR];
    float nb[TILE];
    float na[TILE];
};

__global__ __launch_bounds__(256) void dist_kernel(const float* __restrict__ A,
                                                   const float* __restrict__ Bm) {
    __shared__ DistSmem sm;
    const int tid  = threadIdx.x;
    const int wid  = tid >> 5;
    const int lane = tid & 31;
    const int bz    = blockIdx.z;
    const int iTile = blockIdx.x * TILE;
    const int jTile = blockIdx.y * TILE;

    const uint32_t s_b = smem_u32(sm.bmat);
    const uint32_t s_a = smem_u32(sm.amat);

    const int r = tid >> 1;
    const int h = tid & 1;
    const float* arow = A  + ((size_t)bz * NSEQ + iTile + r) * DDIM + h * 32;
    const float* brow = Bm + ((size_t)bz * MSEQ + jTile + r) * DDIM + h * 32;

    const int j0 = (wid >> 1) * 32;
    const int i0 = (wid & 1) * 64;

    float sa = 0.0f, sb = 0.0f;
    float acc[2][8][4];
#pragma unroll
    for (int fi = 0; fi < 2; fi++)
#pragma unroll
        for (int fn = 0; fn < 8; fn++)
#pragma unroll
            for (int e = 0; e < 4; e++) acc[fi][fn][e] = 0.0f;

    const int aAddrRow = j0 + (lane & 15);
    const int aAddrCol = (lane >> 4) << 3;
    const int bAddrRow = i0 + ((lane >> 4) << 3) + (lane & 7);
    const int bAddrCol = ((lane >> 3) & 1) << 3;

#pragma unroll
    for (int half = 0; half < 2; half++) {
        const int k0 = half * KH;
#pragma unroll
        for (int i = 0; i < 8; i++) {
            const int col = h * 32 + i * 4;
            float4 va = *(const float4*)(arow + k0 + i * 4);
            sa += va.x * va.x + va.y * va.y + va.z * va.z + va.w * va.w;
            *(uint2*)&sm.amat[r * SMSTR + col] =
                make_uint2(f2bf2(va.x, va.y), f2bf2(va.z, va.w));
            float4 vb = *(const float4*)(brow + k0 + i * 4);
            sb += vb.x * vb.x + vb.y * vb.y + vb.z * vb.z + vb.w * vb.w;
            *(uint2*)&sm.bmat[r * SMSTR + col] =
                make_uint2(f2bf2(-2.0f * vb.x, -2.0f * vb.y),
                           f2bf2(-2.0f * vb.z, -2.0f * vb.w));
        }
        __syncthreads();

#pragma unroll
        for (int kk = 0; kk < 4; kk++) {
            const int koff = kk * 16;
            uint32_t af[2][4];
#pragma unroll
            for (int fi = 0; fi < 2; fi++)
                ldsm4(af[fi][0], af[fi][1], af[fi][2], af[fi][3],
                      s_b + (uint32_t)(((aAddrRow + fi * 16) * SMSTR + koff + aAddrCol) * 2));
            uint32_t bf[8][2];
#pragma unroll
            for (int g = 0; g < 4; g++) {
                uint32_t q0, q1, q2, q3;
                ldsm4(q0, q1, q2, q3,
                      s_a + (uint32_t)(((bAddrRow + g * 16) * SMSTR + koff + bAddrCol) * 2));
                bf[2 * g][0] = q0; bf[2 * g][1] = q1;
                bf[2 * g + 1][0] = q2; bf[2 * g + 1][1] = q3;
            }
#pragma unroll
            for (int fi = 0; fi < 2; fi++)
#pragma unroll
                for (int fn = 0; fn < 8; fn++)
                    mma16816(acc[fi][fn], af[fi], bf[fn]);
        }
        __syncthreads();
    }

    sa += __shfl_xor_sync(0xffffffffu, sa, 1);
    sb += __shfl_xor_sync(0xffffffffu, sb, 1);
    if (h == 0) { sm.na[r] = sa; sm.nb[r] = sb; }
    __syncthreads();

    const int jq = lane >> 2;
    const int ip = (lane & 3) * 2;
    float* Drow = g_D + ((size_t)bz * MSEQ + jTile) * NSEQ + iTile;
#pragma unroll
    for (int fi = 0; fi < 2; fi++) {
        const int jl = j0 + fi * 16 + jq;
        const float nb0 = sm.nb[jl];
        const float nb1 = sm.nb[jl + 8];
#pragma unroll
        for (int fn = 0; fn < 8; fn++) {
            const int il = i0 + fn * 8 + ip;
            const float na0 = sm.na[il];
            const float na1 = sm.na[il + 1];
            float2 v0 = make_float2(nb0 + na0 + acc[fi][fn][0],
                                    nb0 + na1 + acc[fi][fn][1]);
            float2 v1 = make_float2(nb1 + na0 + acc[fi][fn][2],
                                    nb1 + na1 + acc[fi][fn][3]);
            *(float2*)&Drow[(size_t)jl * NSEQ + il]       = v0;
            *(float2*)&Drow[(size_t)(jl + 8) * NSEQ + il] = v1;
        }
    }
}

// ---------------------------------------------------------------------------
// Kernel 2: soft-DTW — lagged-band scheme (R13 structure, FIXED pipeline).
// 4 warps x 96 columns; lane owns 3 adjacent columns (c1=96w+3*lane+1,+2,+3).
// Warp w lags warp w-1 by 31 gens: at slot T, g = T + 2 - 31*w. Every ring
// value needed was produced >= 32 slots earlier => strictly earlier 32-slot
// round => one __syncthreads per round (27 total).
// D pipeline: double buffer, lookahead-1. At the boundary where chunk mc
// begins consumption, issue chunk mc+1 into buffer (mc+1)&1 (freed by chunk
// mc-1), commit, CP_WAIT1 (=> chunk mc landed), __syncwarp.
// ---------------------------------------------------------------------------
#define DW 4
#define QR 32
#define NROUNDS 27           // ceil((127*3 + 479)/32)
#define DCH 8
#define NCHUNKS 60           // 479 gens per band window, 60*8 = 480

__device__ __forceinline__ float softmin_cell(float rd, float ru, float rl, float d) {
    float mn = fminf(rd, fminf(ru, rl));
    float mx = fmaxf(rd, fmaxf(ru, rl));
    float md = (rd + ru + rl) - mn - mx;
    float s  = 1.0f + __expf(mn - md) + __expf(mn - mx);
    return d + (mn - __logf(s));
}

__device__ __forceinline__ void issue_chunk(float* __restrict__ dst, int w, int cb,
                                            int lane, const float* __restrict__ Db) {
    const int rsub = lane >> 3;          // 0..3
    const int e    = lane & 7;           // 0..7
#pragma unroll
    for (int a = 0; a < 24; a++) {
        int idx = a * 4 + rsub;          // 0..95
        int row = 96 * w + idx;
        int im1 = cb - row - 2 + e;
        int imc = im1 < 0 ? 0 : (im1 > NSEQ - 1 ? NSEQ - 1 : im1);
        uint32_t ok = (im1 >= 0 && im1 < NSEQ) ? 4u : 0u;
        cp_async4(smem_u32(dst + idx * 9 + e), Db + (size_t)row * NSEQ + imc, ok);
    }
}

__global__ __launch_bounds__(128) void dtw_kernel(float* __restrict__ out) {
    __shared__ float s_ring[3][772];
    __shared__ float s_Dbuf[DW][2][96 * 9];   // 96 rows x 8 elems, pad stride 9

    const int bz = blockIdx.x;
    const int t = threadIdx.x;
    const int w = t >> 5, lane = t & 31;
    const float* __restrict__ Db = g_D + (size_t)bz * MSEQ * NSEQ;

    const int c1 = 96 * w + 3 * lane + 1;          // lane's first column
    const int W0 = 96 * w + 2;                     // first gen of band window
    const int W1 = 96 * w + 480;                   // last gen (lane31 c3 i=384)

    // Pre-issue D chunks 0 and 1 for this warp (chunk m -> buffer m&1).
    issue_chunk(&s_Dbuf[w][0][0], w, W0, lane, Db);
    CP_COMMIT();
    issue_chunk(&s_Dbuf[w][1][0], w, W0 + DCH, lane, Db);
    CP_COMMIT();

    int next_cb = W0;          // next consume-boundary gen

    float v1 = INF_V, v2 = INF_V, v3 = INF_V;      // V(g-1, c1..c3)
    float v1_pp = INF_V, v2_pp = INF_V;            // V(g-2, c1..c2)
    float l3_prev = INF_V;                         // V(g-2, c1-1)

    for (int r = 0; r < NROUNDS; r++) {
#pragma unroll 4
        for (int s = 0; s < QR; s++) {
            const int T = r * QR + s;
            const int g = T + 2 - 31 * w;
            if (g >= W0 && g <= W1) {              // warp-uniform
                if (g == next_cb) {                // boundary: start chunk mc
                    const int mc = (next_cb - W0) >> 3;
                    const int mi = mc + 1;         // lookahead-1 issue
                    if (mi >= 2 && mi < NCHUNKS)   // 0,1 pre-issued
                        issue_chunk(&s_Dbuf[w][mi & 1][0], w,
                                    W0 + mi * DCH, lane, Db);
                    CP_COMMIT();                   // (possibly empty group)
                    CP_WAIT1();                    // chunk mc complete
                    __syncwarp();
                    next_cb += DCH;
                }
                const int e = g - (next_cb - DCH);           // 0..7
                const int cbuf = ((g - W0) >> 3) & 1;
                const float* Dc = &s_Dbuf[w][cbuf][3 * lane * 9];
                float d1 = Dc[0 * 9 + e];
                float d2 = Dc[1 * 9 + e];
                float d3 = Dc[2 * 9 + e];

                float l3 = __shfl_up_sync(0xffffffffu, v3, 1); // V(g-1, c1-1)
                float dg1 = l3_prev;                            // V(g-2, c1-1)
                if (lane == 0) {
                    l3  = (w > 0) ? s_ring[w - 1][g - 1] : INF_V;
                    dg1 = (w > 0) ? s_ring[w - 1][g - 2]
                                  : ((g == 2) ? 0.0f : INF_V);  // R[0][0]
                }

                float n1 = softmin_cell(dg1,   v1, l3, d1);
                float n2 = softmin_cell(v1_pp, v2, v1, d2);
                float n3 = softmin_cell(v2_pp, v3, v2, d3);

                const int i1 = g - c1;
                n1 = (i1 >= 1 && i1 <= NSEQ)     ? n1 : INF_V;
                n2 = (i1 >= 2 && i1 <= NSEQ + 1) ? n2 : INF_V;
                n3 = (i1 >= 3 && i1 <= NSEQ + 2) ? n3 : INF_V;

                l3_prev = l3;
                v1_pp = v1; v2_pp = v2;
                v1 = n1; v2 = n2; v3 = n3;

                if (w < 3 && lane == 31) s_ring[w][g] = n3;     // band boundary
                if (w == 3 && lane == 31 && g == NSEQ + MSEQ)   // R[N][M]
                    out[bz] = n3;
            }
        }
        __syncthreads();       // publishes ring rounds; lag guarantees coverage
    }
}

// ---------------------------------------------------------------------------
// Launch
// ---------------------------------------------------------------------------
extern "C" void kernel_launch(void* const* d_in, const int* in_sizes, int n_in,
                              void* d_out, int out_size) {
    const float* a = (const float*)d_in[0];
    const float* b = (const float*)d_in[1];
    float* out = (float*)d_out;

    dim3 gdist(NSEQ / TILE, MSEQ / TILE, BATCH);   // (3,3,128)
    dist_kernel<<<gdist, 256>>>(a, b);

    dtw_kernel<<<BATCH, 128>>>(out);
}

// round 16
// speedup vs baseline: 1.1880x; 1.1880x over previous
#include <cuda_runtime.h>
#include <cuda_bf16.h>
#include <cstdint>

// Problem constants
#define BATCH 128
#define NSEQ  384
#define MSEQ  384
#define DDIM  128
#define LOG2E 1.4426950408889634f
#define LN2   0.6931471805599453f
#define INF2  (1000000.0f * LOG2E)     // pseudo-INF in log2-scaled domain

// g_D TRANSPOSED + SCALED: g_D[b][j][i] = ||a_i - b_j||^2 * LOG2E, contiguous in i.
__device__ float g_D[(size_t)BATCH * MSEQ * NSEQ];

// ---------------------------------------------------------------------------
// PTX helpers — generic compute_80+ PTX only.
// ---------------------------------------------------------------------------
__device__ __forceinline__ uint32_t smem_u32(const void* p) {
    uint32_t a;
    asm("{ .reg .u64 t; cvta.to.shared.u64 t, %1; cvt.u32.u64 %0, t; }" : "=r"(a) : "l"(p));
    return a;
}
__device__ __forceinline__ uint32_t f2bf2(float lo, float hi) {
    uint32_t r;
    asm("cvt.rn.bf16x2.f32 %0, %1, %2;" : "=r"(r) : "f"(hi), "f"(lo));
    return r;
}
__device__ __forceinline__ void ldsm4(uint32_t& r0, uint32_t& r1, uint32_t& r2,
                                      uint32_t& r3, uint32_t addr) {
    asm volatile("ldmatrix.sync.aligned.m8n8.x4.shared.b16 {%0,%1,%2,%3}, [%4];"
                 : "=r"(r0), "=r"(r1), "=r"(r2), "=r"(r3) : "r"(addr));
}
__device__ __forceinline__ void mma16816(float* c, const uint32_t* a, const uint32_t* b) {
    asm volatile("mma.sync.aligned.m16n8k16.row.col.f32.bf16.bf16.f32 "
                 "{%0,%1,%2,%3}, {%4,%5,%6,%7}, {%8,%9}, {%0,%1,%2,%3};"
                 : "+f"(c[0]), "+f"(c[1]), "+f"(c[2]), "+f"(c[3])
                 : "r"(a[0]), "r"(a[1]), "r"(a[2]), "r"(a[3]), "r"(b[0]), "r"(b[1]));
}
__device__ __forceinline__ void cp_async4(uint32_t dst, const void* src, uint32_t srcsz) {
    asm volatile("cp.async.ca.shared.global [%0], [%1], 4, %2;"
                 :: "r"(dst), "l"(src), "r"(srcsz) : "memory");
}
#define CP_COMMIT() asm volatile("cp.async.commit_group;" ::: "memory")
#define CP_WAIT1()  asm volatile("cp.async.wait_group 1;" ::: "memory")
__device__ __forceinline__ float ex2(float x) {
    float y; asm("ex2.approx.f32 %0, %1;" : "=f"(y) : "f"(x)); return y;
}
__device__ __forceinline__ float lg2(float x) {
    float y; asm("lg2.approx.f32 %0, %1;" : "=f"(y) : "f"(x)); return y;
}

// ---------------------------------------------------------------------------
// Kernel 1: fused norms + pairwise distances via bf16 HMMA (R11 structure;
// epilogue scaled by LOG2E for the log2-domain DP).
// ---------------------------------------------------------------------------
#define TILE 128
#define KH   64
#define SMSTR 72

struct __align__(16) DistSmem {
    __nv_bfloat16 bmat[TILE * SMSTR];
    __nv_bfloat16 amat[TILE * SMSTR];
    float nb[TILE];
    float na[TILE];
};

__global__ __launch_bounds__(256) void dist_kernel(const float* __restrict__ A,
                                                   const float* __restrict__ Bm) {
    __shared__ DistSmem sm;
    const int tid  = threadIdx.x;
    const int wid  = tid >> 5;
    const int lane = tid & 31;
    const int bz    = blockIdx.z;
    const int iTile = blockIdx.x * TILE;
    const int jTile = blockIdx.y * TILE;

    const uint32_t s_b = smem_u32(sm.bmat);
    const uint32_t s_a = smem_u32(sm.amat);

    const int r = tid >> 1;
    const int h = tid & 1;
    const float* arow = A  + ((size_t)bz * NSEQ + iTile + r) * DDIM + h * 32;
    const float* brow = Bm + ((size_t)bz * MSEQ + jTile + r) * DDIM + h * 32;

    const int j0 = (wid >> 1) * 32;
    const int i0 = (wid & 1) * 64;

    float sa = 0.0f, sb = 0.0f;
    float acc[2][8][4];
#pragma unroll
    for (int fi = 0; fi < 2; fi++)
#pragma unroll
        for (int fn = 0; fn < 8; fn++)
#pragma unroll
            for (int e = 0; e < 4; e++) acc[fi][fn][e] = 0.0f;

    const int aAddrRow = j0 + (lane & 15);
    const int aAddrCol = (lane >> 4) << 3;
    const int bAddrRow = i0 + ((lane >> 4) << 3) + (lane & 7);
    const int bAddrCol = ((lane >> 3) & 1) << 3;

#pragma unroll
    for (int half = 0; half < 2; half++) {
        const int k0 = half * KH;
#pragma unroll
        for (int i = 0; i < 8; i++) {
            const int col = h * 32 + i * 4;
            float4 va = *(const float4*)(arow + k0 + i * 4);
            sa += va.x * va.x + va.y * va.y + va.z * va.z + va.w * va.w;
            *(uint2*)&sm.amat[r * SMSTR + col] =
                make_uint2(f2bf2(va.x, va.y), f2bf2(va.z, va.w));
            float4 vb = *(const float4*)(brow + k0 + i * 4);
            sb += vb.x * vb.x + vb.y * vb.y + vb.z * vb.z + vb.w * vb.w;
            *(uint2*)&sm.bmat[r * SMSTR + col] =
                make_uint2(f2bf2(-2.0f * vb.x, -2.0f * vb.y),
                           f2bf2(-2.0f * vb.z, -2.0f * vb.w));
        }
        __syncthreads();

#pragma unroll
        for (int kk = 0; kk < 4; kk++) {
            const int koff = kk * 16;
            uint32_t af[2][4];
#pragma unroll
            for (int fi = 0; fi < 2; fi++)
                ldsm4(af[fi][0], af[fi][1], af[fi][2], af[fi][3],
                      s_b + (uint32_t)(((aAddrRow + fi * 16) * SMSTR + koff + aAddrCol) * 2));
            uint32_t bf[8][2];
#pragma unroll
            for (int g = 0; g < 4; g++) {
                uint32_t q0, q1, q2, q3;
                ldsm4(q0, q1, q2, q3,
                      s_a + (uint32_t)(((bAddrRow + g * 16) * SMSTR + koff + bAddrCol) * 2));
                bf[2 * g][0] = q0; bf[2 * g][1] = q1;
                bf[2 * g + 1][0] = q2; bf[2 * g + 1][1] = q3;
            }
#pragma unroll
            for (int fi = 0; fi < 2; fi++)
#pragma unroll
                for (int fn = 0; fn < 8; fn++)
                    mma16816(acc[fi][fn], af[fi], bf[fn]);
        }
        __syncthreads();
    }

    sa += __shfl_xor_sync(0xffffffffu, sa, 1);
    sb += __shfl_xor_sync(0xffffffffu, sb, 1);
    if (h == 0) { sm.na[r] = sa; sm.nb[r] = sb; }
    __syncthreads();

    const int jq = lane >> 2;
    const int ip = (lane & 3) * 2;
    float* Drow = g_D + ((size_t)bz * MSEQ + jTile) * NSEQ + iTile;
#pragma unroll
    for (int fi = 0; fi < 2; fi++) {
        const int jl = j0 + fi * 16 + jq;
        const float nb0 = sm.nb[jl];
        const float nb1 = sm.nb[jl + 8];
#pragma unroll
        for (int fn = 0; fn < 8; fn++) {
            const int il = i0 + fn * 8 + ip;
            const float na0 = sm.na[il];
            const float na1 = sm.na[il + 1];
            float2 v0 = make_float2((nb0 + na0 + acc[fi][fn][0]) * LOG2E,
                                    (nb0 + na1 + acc[fi][fn][1]) * LOG2E);
            float2 v1 = make_float2((nb1 + na0 + acc[fi][fn][2]) * LOG2E,
                                    (nb1 + na1 + acc[fi][fn][3]) * LOG2E);
            *(float2*)&Drow[(size_t)jl * NSEQ + il]       = v0;
            *(float2*)&Drow[(size_t)(jl + 8) * NSEQ + il] = v1;
        }
    }
}

// ---------------------------------------------------------------------------
// Kernel 2: soft-DTW — lagged-band, 12 warps x 32 cols, 1 cell/lane.
// Lane owns column c = 32w + lane + 1 (D row c-1 = 32w+lane, contiguous i).
// Slot clock: u = T - 39w; gen g = 32w + 2 + u; active u in [0,414].
// Cell (g,c): up = v (own prev), left = shfl_up(v) [lane0: ring],
//             diag = l_prev (last slot's left) — zero extra loads.
// Lag 7 >= QR-1=7: ring value read at slot T was written at T-8 => previous
// 8-slot round => one __syncthreads per round (106 total) suffices.
// Ring circular 32 entries/warp: same-round writes land +8..+15 mod 32 ahead
// of reads — disjoint. D staged per-lane (own row) via cp.async double buffer,
// lookahead-1 (chunk mc starts -> issue mc+1 into buf (mc+1)&1, WAIT1).
// All DP values in log2 domain (x LOG2E); output unscaled by LN2.
// ---------------------------------------------------------------------------
#define NW 12
#define WIN 415           // active slots per warp (u = 0..414)
#define NCH 52            // ceil(415/8)
#define NROUNDS 106       // ceil((39*11 + 415)/8)

__device__ __forceinline__ void stage_chunk(float* __restrict__ dst,
                                            const float* __restrict__ Dsrc,
                                            int m, int lane) {
#pragma unroll
    for (int e = 0; e < 8; e++) {
        int idx = 8 * m + e - lane;              // i-1 for this element
        int idc = idx < 0 ? 0 : (idx > NSEQ - 1 ? NSEQ - 1 : idx);
        uint32_t ok = (idx >= 0 && idx < NSEQ) ? 4u : 0u;
        cp_async4(smem_u32(dst + lane * 9 + e), Dsrc + idc, ok);
    }
}

__global__ __launch_bounds__(384) void dtw_kernel(float* __restrict__ out) {
    __shared__ float s_ring[NW + 1][32];       // warp w reads [w], writes [w+1]
    __shared__ float s_Dbuf[NW][2][32 * 9];    // per-warp double buffer, pad 9

    const int bz = blockIdx.x;
    const int t = threadIdx.x;
    const int w = t >> 5, lane = t & 31;
    const float* __restrict__ Dsrc =
        g_D + (size_t)bz * MSEQ * NSEQ + (size_t)(32 * w + lane) * NSEQ;

    // Pre-issue chunks 0,1 (chunk m -> buffer m&1).
    stage_chunk(&s_Dbuf[w][0][0], Dsrc, 0, lane); CP_COMMIT();
    stage_chunk(&s_Dbuf[w][1][0], Dsrc, 1, lane); CP_COMMIT();

    float v = INF2;                            // V(g-1, c)
    float lprev = (t == 0) ? 0.0f : INF2;      // V(g-2, c-1); R[0][0]=0 seed
    int u  = -39 * w;                          // slot clock
    int iv = u - lane;                         // i-1 = u - lane
    const float* dptr = &s_Dbuf[w][0][lane * 9];

    __syncthreads();

    for (int r = 0; r < NROUNDS; r++) {
#pragma unroll
        for (int s = 0; s < 8; s++) {
            if (u >= 0 && u < WIN) {                       // warp-uniform
                if ((u & 7) == 0) {                        // chunk boundary
                    const int mc = u >> 3;
                    const int mi = mc + 1;                 // lookahead-1
                    if (mi >= 2 && mi < NCH)
                        stage_chunk(&s_Dbuf[w][mi & 1][0], Dsrc, mi, lane);
                    CP_COMMIT();                           // (possibly empty)
                    CP_WAIT1();                            // chunk mc landed
                    dptr = &s_Dbuf[w][mc & 1][lane * 9];
                }
                float d = *dptr++;                         // own-lane staged
                float l = __shfl_up_sync(0xffffffffu, v, 1);
                float rv = s_ring[w][(u + 1) & 31];        // broadcast LDS
                if (lane == 0) l = (w > 0) ? rv : INF2;

                float mn = fminf(lprev, fminf(v, l));
                float mx = fmaxf(lprev, fmaxf(v, l));
                float md = (lprev + v + l) - mn - mx;
                float sum = 1.0f + ex2(mn - md) + ex2(mn - mx);
                float n = d + (mn - lg2(sum));
                n = (iv >= 0 && iv < NSEQ) ? n : INF2;     // validity select

                lprev = l;
                v = n;
                if (lane == 31) s_ring[w + 1][(u + 2) & 31] = n;  // gen g
                if (w == NW - 1 && lane == 31 && u == WIN - 1)
                    out[bz] = n * LN2;                     // R[N][M] unscaled
            }
            u++; iv++;
        }
        __syncthreads();       // publishes ring round; lag covers the rest
    }
}

// ---------------------------------------------------------------------------
// Launch
// ---------------------------------------------------------------------------
extern "C" void kernel_launch(void* const* d_in, const int* in_sizes, int n_in,
                              void* d_out, int out_size) {
    const float* a = (const float*)d_in[0];
    const float* b = (const float*)d_in[1];
    float* out = (float*)d_out;

    dim3 gdist(NSEQ / TILE, MSEQ / TILE, BATCH);   // (3,3,128)
    dist_kernel<<<gdist, 256>>>(a, b);

    dtw_kernel<<<BATCH, 384>>>(out);
}

// round 17
// speedup vs baseline: 1.3849x; 1.1657x over previous
#include <cuda_runtime.h>
#include <cuda_bf16.h>
#include <cstdint>

// Problem constants
#define BATCH 128
#define NSEQ  384
#define MSEQ  384
#define DDIM  128
#define LOG2E 1.4426950408889634f
#define LN2   0.6931471805599453f
#define INF2  (1000000.0f * LOG2E)     // pseudo-INF in log2-scaled domain

// g_D TRANSPOSED + SCALED: g_D[b][j][i] = ||a_i - b_j||^2 * LOG2E, contiguous in i.
__device__ float g_D[(size_t)BATCH * MSEQ * NSEQ];

// ---------------------------------------------------------------------------
// PTX helpers — generic compute_80+ PTX only.
// ---------------------------------------------------------------------------
__device__ __forceinline__ uint32_t smem_u32(const void* p) {
    uint32_t a;
    asm("{ .reg .u64 t; cvta.to.shared.u64 t, %1; cvt.u32.u64 %0, t; }" : "=r"(a) : "l"(p));
    return a;
}
__device__ __forceinline__ uint32_t f2bf2(float lo, float hi) {
    uint32_t r;
    asm("cvt.rn.bf16x2.f32 %0, %1, %2;" : "=r"(r) : "f"(hi), "f"(lo));
    return r;
}
__device__ __forceinline__ void ldsm4(uint32_t& r0, uint32_t& r1, uint32_t& r2,
                                      uint32_t& r3, uint32_t addr) {
    asm volatile("ldmatrix.sync.aligned.m8n8.x4.shared.b16 {%0,%1,%2,%3}, [%4];"
                 : "=r"(r0), "=r"(r1), "=r"(r2), "=r"(r3) : "r"(addr));
}
__device__ __forceinline__ void mma16816(float* c, const uint32_t* a, const uint32_t* b) {
    asm volatile("mma.sync.aligned.m16n8k16.row.col.f32.bf16.bf16.f32 "
                 "{%0,%1,%2,%3}, {%4,%5,%6,%7}, {%8,%9}, {%0,%1,%2,%3};"
                 : "+f"(c[0]), "+f"(c[1]), "+f"(c[2]), "+f"(c[3])
                 : "r"(a[0]), "r"(a[1]), "r"(a[2]), "r"(a[3]), "r"(b[0]), "r"(b[1]));
}
__device__ __forceinline__ void cp_async16(uint32_t dst, const void* src, uint32_t srcsz) {
    asm volatile("cp.async.ca.shared.global [%0], [%1], 16, %2;"
                 :: "r"(dst), "l"(src), "r"(srcsz) : "memory");
}
#define CP_COMMIT() asm volatile("cp.async.commit_group;" ::: "memory")
#define CP_WAIT1()  asm volatile("cp.async.wait_group 1;" ::: "memory")
__device__ __forceinline__ float ex2(float x) {
    float y; asm("ex2.approx.f32 %0, %1;" : "=f"(y) : "f"(x)); return y;
}
__device__ __forceinline__ float lg2(float x) {
    float y; asm("lg2.approx.f32 %0, %1;" : "=f"(y) : "f"(x)); return y;
}

// ---------------------------------------------------------------------------
// Kernel 1: fused norms + pairwise distances via bf16 HMMA (unchanged R16).
// ---------------------------------------------------------------------------
#define TILE 128
#define KH   64
#define SMSTR 72

struct __align__(16) DistSmem {
    __nv_bfloat16 bmat[TILE * SMSTR];
    __nv_bfloat16 amat[TILE * SMSTR];
    float nb[TILE];
    float na[TILE];
};

__global__ __launch_bounds__(256) void dist_kernel(const float* __restrict__ A,
                                                   const float* __restrict__ Bm) {
    __shared__ DistSmem sm;
    const int tid  = threadIdx.x;
    const int wid  = tid >> 5;
    const int lane = tid & 31;
    const int bz    = blockIdx.z;
    const int iTile = blockIdx.x * TILE;
    const int jTile = blockIdx.y * TILE;

    const uint32_t s_b = smem_u32(sm.bmat);
    const uint32_t s_a = smem_u32(sm.amat);

    const int r = tid >> 1;
    const int h = tid & 1;
    const float* arow = A  + ((size_t)bz * NSEQ + iTile + r) * DDIM + h * 32;
    const float* brow = Bm + ((size_t)bz * MSEQ + jTile + r) * DDIM + h * 32;

    const int j0 = (wid >> 1) * 32;
    const int i0 = (wid & 1) * 64;

    float sa = 0.0f, sb = 0.0f;
    float acc[2][8][4];
#pragma unroll
    for (int fi = 0; fi < 2; fi++)
#pragma unroll
        for (int fn = 0; fn < 8; fn++)
#pragma unroll
            for (int e = 0; e < 4; e++) acc[fi][fn][e] = 0.0f;

    const int aAddrRow = j0 + (lane & 15);
    const int aAddrCol = (lane >> 4) << 3;
    const int bAddrRow = i0 + ((lane >> 4) << 3) + (lane & 7);
    const int bAddrCol = ((lane >> 3) & 1) << 3;

#pragma unroll
    for (int half = 0; half < 2; half++) {
        const int k0 = half * KH;
#pragma unroll
        for (int i = 0; i < 8; i++) {
            const int col = h * 32 + i * 4;
            float4 va = *(const float4*)(arow + k0 + i * 4);
            sa += va.x * va.x + va.y * va.y + va.z * va.z + va.w * va.w;
            *(uint2*)&sm.amat[r * SMSTR + col] =
                make_uint2(f2bf2(va.x, va.y), f2bf2(va.z, va.w));
            float4 vb = *(const float4*)(brow + k0 + i * 4);
            sb += vb.x * vb.x + vb.y * vb.y + vb.z * vb.z + vb.w * vb.w;
            *(uint2*)&sm.bmat[r * SMSTR + col] =
                make_uint2(f2bf2(-2.0f * vb.x, -2.0f * vb.y),
                           f2bf2(-2.0f * vb.z, -2.0f * vb.w));
        }
        __syncthreads();

#pragma unroll
        for (int kk = 0; kk < 4; kk++) {
            const int koff = kk * 16;
            uint32_t af[2][4];
#pragma unroll
            for (int fi = 0; fi < 2; fi++)
                ldsm4(af[fi][0], af[fi][1], af[fi][2], af[fi][3],
                      s_b + (uint32_t)(((aAddrRow + fi * 16) * SMSTR + koff + aAddrCol) * 2));
            uint32_t bf[8][2];
#pragma unroll
            for (int g = 0; g < 4; g++) {
                uint32_t q0, q1, q2, q3;
                ldsm4(q0, q1, q2, q3,
                      s_a + (uint32_t)(((bAddrRow + g * 16) * SMSTR + koff + bAddrCol) * 2));
                bf[2 * g][0] = q0; bf[2 * g][1] = q1;
                bf[2 * g + 1][0] = q2; bf[2 * g + 1][1] = q3;
            }
#pragma unroll
            for (int fi = 0; fi < 2; fi++)
#pragma unroll
                for (int fn = 0; fn < 8; fn++)
                    mma16816(acc[fi][fn], af[fi], bf[fn]);
        }
        __syncthreads();
    }

    sa += __shfl_xor_sync(0xffffffffu, sa, 1);
    sb += __shfl_xor_sync(0xffffffffu, sb, 1);
    if (h == 0) { sm.na[r] = sa; sm.nb[r] = sb; }
    __syncthreads();

    const int jq = lane >> 2;
    const int ip = (lane & 3) * 2;
    float* Drow = g_D + ((size_t)bz * MSEQ + jTile) * NSEQ + iTile;
#pragma unroll
    for (int fi = 0; fi < 2; fi++) {
        const int jl = j0 + fi * 16 + jq;
        const float nb0 = sm.nb[jl];
        const float nb1 = sm.nb[jl + 8];
#pragma unroll
        for (int fn = 0; fn < 8; fn++) {
            const int il = i0 + fn * 8 + ip;
            const float na0 = sm.na[il];
            const float na1 = sm.na[il + 1];
            float2 v0 = make_float2((nb0 + na0 + acc[fi][fn][0]) * LOG2E,
                                    (nb0 + na1 + acc[fi][fn][1]) * LOG2E);
            float2 v1 = make_float2((nb1 + na0 + acc[fi][fn][2]) * LOG2E,
                                    (nb1 + na1 + acc[fi][fn][3]) * LOG2E);
            *(float2*)&Drow[(size_t)jl * NSEQ + il]       = v0;
            *(float2*)&Drow[(size_t)(jl + 8) * NSEQ + il] = v1;
        }
    }
}

// ---------------------------------------------------------------------------
// Kernel 2: soft-DTW — lagged-band (R16 dataflow) with coalesced i-aligned
// D staging and register ring-prefetch.
// 12 warps x 32 cols, 1 cell/lane: col c = 32w + lane + 1; gen g = 32w+2+u;
// slot clock u = T - 40w (LAG 40 >= 39, multiple of 8 so chunk boundaries
// align with rounds). Per-row ring of 3 i-aligned 8-elem blocks: block B
// holds D[row][8B..8B+8) at slot (B mod 3); NSEQ % 8 == 0 => blocks are
// fully valid or fully invalid (cp.async16 src-size 16/0, no straddle).
// Refill per round: 2 cp.async16 per lane (16 rows x 32B contiguous) — 32
// L1 wavefronts/warp/round vs 256 in R16. Block B's staging round is
// strictly after block B-3's last consume round (same-warp ordering).
// Ring values for the whole round prefetched into registers at round top
// (all producers >= 2 rounds old by the lag proof).
// ---------------------------------------------------------------------------
#define NW 12
#define LAG 40
#define WIN 415
#define NROUNDS 107          // ceil((40*11 + 415)/8)

__device__ __forceinline__ void refill(float* __restrict__ dstW,
                                       const float* __restrict__ DbW,
                                       int u0, int lane) {
#pragma unroll
    for (int q = 0; q < 2; q++) {
        int row  = 16 * q + (lane >> 1);
        int half = lane & 1;
        int br  = ((u0 - row) >> 3) + 2;          // signed floor div
        int brc = br < 0 ? 0 : (br > 47 ? 47 : br);
        int brm = br % 3; if (brm < 0) brm += 3;  // mathematical mod
        const float* src = DbW + (size_t)row * NSEQ + 8 * brc + 4 * half;
        uint32_t dst = smem_u32(dstW + row * 24 + brm * 8 + 4 * half);
        uint32_t sz = (br >= 0 && br < 48) ? 16u : 0u;
        cp_async16(dst, src, sz);
    }
}

__global__ __launch_bounds__(384, 1) void dtw_kernel(float* __restrict__ out) {
    __shared__ float s_ring[NW + 1][32];       // warp w reads [w], writes [w+1]
    __shared__ float s_D[NW][32 * 24];         // [warp][row*24 + (i mod 24)]

    const int bz = blockIdx.x;
    const int t = threadIdx.x;
    const int w = t >> 5, lane = t & 31;
    const float* __restrict__ DbW =
        g_D + (size_t)bz * MSEQ * NSEQ + (size_t)(32 * w) * NSEQ;
    float* dstW = &s_D[w][0];

    // Pre-issue the first two virtual rounds' blocks.
    refill(dstW, DbW, -16, lane); CP_COMMIT();
    refill(dstW, DbW, -8, lane);  CP_COMMIT();

    float v = INF2;                            // V(g-1, c)
    float lprev = (t == 0) ? 0.0f : INF2;      // V(g-2, c-1); seeds R[0][0]=0
    int u  = -LAG * w;                         // slot clock
    int iv = u - lane;                         // D element index i-1
    int im = ((iv % 24) + 24) % 24;            // iv mod 24 (rolling)

    __syncthreads();

    for (int r = 0; r < NROUNDS; r++) {
        const int u0 = u;                      // round-top u (multiple of 8)
        const bool act = (u0 >= 0) && (u0 < WIN);
        float rv[8];
        if (act) {
            refill(dstW, DbW, u0, lane);
            CP_COMMIT();
            CP_WAIT1();                        // all prior rounds' blocks landed
            __syncwarp();                      // cross-lane smem visibility
#pragma unroll
            for (int s2 = 0; s2 < 8; s2++)     // broadcast LDS -> registers
                rv[s2] = s_ring[w][(u0 + 1 + s2) & 31];
        }
#pragma unroll
        for (int s2 = 0; s2 < 8; s2++) {
            if (act && u < WIN) {
                float d = s_D[w][lane * 24 + im];          // off-chain LDS
                float l = __shfl_up_sync(0xffffffffu, v, 1);
                if (lane == 0) l = (w > 0) ? rv[s2] : INF2;
                float mn = fminf(lprev, fminf(v, l));
                float mx = fmaxf(lprev, fmaxf(v, l));
                float md = (lprev + v + l) - mn - mx;
                float sm2 = 1.0f + ex2(mn - md) + ex2(mn - mx);
                float n = d + (mn - lg2(sm2));
                n = ((unsigned)iv < (unsigned)NSEQ) ? n : INF2;
                lprev = l;
                v = n;
                if (lane == 31) s_ring[w + 1][(u + 2) & 31] = n;
                if (w == NW - 1 && lane == 31 && u == WIN - 1)
                    out[bz] = n * LN2;                     // R[N][M]
            }
            u++; iv++;
            im = (im == 23) ? 0 : im + 1;
        }
        __syncthreads();       // publishes ring round; lag covers the rest
    }
}

// ---------------------------------------------------------------------------
// Launch
// ---------------------------------------------------------------------------
extern "C" void kernel_launch(void* const* d_in, const int* in_sizes, int n_in,
                              void* d_out, int out_size) {
    const float* a = (const float*)d_in[0];
    const float* b = (const float*)d_in[1];
    float* out = (float*)d_out;

    dim3 gdist(NSEQ / TILE, MSEQ / TILE, BATCH);   // (3,3,128)
    dist_kernel<<<gdist, 256>>>(a, b);

    dtw_kernel<<<BATCH, 384>>>(out);
}